// round 8
// baseline (speedup 1.0000x reference)
#include <cuda_runtime.h>
#include <cooperative_groups.h>

namespace cg = cooperative_groups;

#define BATCH    32
#define NPT      100000
#define NSAMP    1024
#define CPB      4                   // CTAs (cluster size) per batch
#define CHUNK    (NPT / CPB)         // 25000 points per CTA
#define TH       512
#define SP       18944               // smem-resident points per CTA (= 37*512)
#define SPT      (SP / TH)           // 37
#define SR       (CHUNK - SP)        // 6056 points streamed from L2
#define SRG      (SR / 4)            // 1514 float4 groups
#define DYN_SMEM (SP * 3 * 4)        // 227328 bytes SoA coords

// SoA copies of the coordinates (scratch; __device__ globals are allowed).
__device__ float g_sx[BATCH * NPT];
__device__ float g_sy[BATCH * NPT];
__device__ float g_sz[BATCH * NPT];

__global__ void soa_transpose(const float* __restrict__ coord, int n) {
    int i = blockIdx.x * blockDim.x + threadIdx.x;
    if (i < n) {
        float x = coord[3 * i + 0];
        float y = coord[3 * i + 1];
        float z = coord[3 * i + 2];
        g_sx[i] = x;
        g_sy[i] = y;
        g_sz[i] = z;
    }
}

struct RedBuf {
    float rd[2][CPB];   // double-buffered cluster candidates (dist)
    int   ri[2][CPB];   // double-buffered cluster candidates (index)
    float sd[16];       // per-warp partials
    int   si[16];
};

__device__ __forceinline__ void combine(float& bd, int& bi, float od, int oi) {
    // argmax with first-occurrence (lowest index) tie-break, matching jnp.argmax
    if (od > bd || (od == bd && oi < bi)) { bd = od; bi = oi; }
}

// XLA:GPU-matching distance: FMA-contracted, left-to-right 3-term reduce:
//   fma(dz, dz, fma(dy, dy, dx*dx))
__device__ __forceinline__ float dist3(float px, float py, float pz,
                                       float cx, float cy, float cz) {
    float dx = __fsub_rn(px, cx);
    float dy = __fsub_rn(py, cy);
    float dz = __fsub_rn(pz, cz);
    return __fmaf_rn(dz, dz, __fmaf_rn(dy, dy, __fmul_rn(dx, dx)));
}

__global__ void __cluster_dims__(CPB, 1, 1) __launch_bounds__(TH, 1)
fps_kernel(const int* __restrict__ finit, float* __restrict__ out)
{
    extern __shared__ float smem[];
    __shared__ RedBuf red;

    cg::cluster_group cluster = cg::this_cluster();
    const int rank = (int)cluster.block_rank();
    const int b    = blockIdx.x / CPB;
    const int tid  = threadIdx.x;
    const int base = rank * CHUNK;

    const float* __restrict__ bx = g_sx + b * NPT;
    const float* __restrict__ by = g_sy + b * NPT;
    const float* __restrict__ bz = g_sz + b * NPT;

    float* sx = smem;
    float* sy = smem + SP;
    float* sz = smem + 2 * SP;

    // Fill smem-resident SoA slab once.
    for (int i = tid; i < SP; i += TH) {
        sx[i] = bx[base + i];
        sy[i] = by[base + i];
        sz[i] = bz[base + i];
    }
    __syncthreads();

    // Streamed tail region (L2-resident), float4 views. All offsets are
    // multiples of 4 floats -> 16B aligned.
    const float4* __restrict__ rx = (const float4*)(bx + base + SP);
    const float4* __restrict__ ry = (const float4*)(by + base + SP);
    const float4* __restrict__ rz = (const float4*)(bz + base + SP);

    // Running min-distance arrays, register-resident.
    float dmin_s[SPT];
    float dmin_r[12];
#pragma unroll
    for (int k = 0; k < SPT; k++) dmin_s[k] = 1e10f;
#pragma unroll
    for (int k = 0; k < 12; k++)  dmin_r[k] = 1e10f;

    // JAX default config: jnp.int64 downgrades to int32 -> seeds are int32.
    int f = finit[b];

    for (int t = 0; t < NSAMP; t++) {
        // Record the incoming (pre-update) centroid index + its coords.
        // Output is float32: indices < 2^24 are exactly representable.
        // Done by a warp-1 thread of rank 0 so it's off the critical path.
        if (rank == 0 && tid == 32) {
            out[b * NSAMP + t] = (float)f;
            float* so = out + BATCH * NSAMP + (b * NSAMP + t) * 3;
            so[0] = bx[f];
            so[1] = by[f];
            so[2] = bz[f];
        }

        const float cx = bx[f];
        const float cy = by[f];
        const float cz = bz[f];

        float bd = -1.0f;        // distances are >= 0
        int   bi = 0x7fffffff;

        // SMEM-resident points. Indices ascend, so strict '>' alone gives the
        // lowest-index tie-break within a thread.
#pragma unroll
        for (int k = 0; k < SPT; k++) {
            const int p = k * TH + tid;
            float dist = dist3(sx[p], sy[p], sz[p], cx, cy, cz);
            float dm = fminf(dmin_s[k], dist);
            dmin_s[k] = dm;
            if (dm > bd) { bd = dm; bi = base + p; }
        }

        // L2-streamed tail, float4 SoA loads.
#pragma unroll
        for (int g = 0; g < 3; g++) {
            const int grp = g * TH + tid;
            if (grp < SRG) {
                float4 x4 = rx[grp];
                float4 y4 = ry[grp];
                float4 z4 = rz[grp];
                const int gi0 = base + SP + grp * 4;
#define FPS_POINT(J, XX, YY, ZZ)                                               \
                {                                                              \
                    float dist = dist3(XX, YY, ZZ, cx, cy, cz);                \
                    float dm = fminf(dmin_r[g * 4 + (J)], dist);               \
                    dmin_r[g * 4 + (J)] = dm;                                  \
                    if (dm > bd) { bd = dm; bi = gi0 + (J); }                  \
                }
                FPS_POINT(0, x4.x, y4.x, z4.x)
                FPS_POINT(1, x4.y, y4.y, z4.y)
                FPS_POINT(2, x4.z, y4.z, z4.z)
                FPS_POINT(3, x4.w, y4.w, z4.w)
#undef FPS_POINT
            }
        }

        // Warp reduction (argmax, ties -> lowest index).
#pragma unroll
        for (int off = 16; off > 0; off >>= 1) {
            float od = __shfl_down_sync(0xffffffffu, bd, off);
            int   oi = __shfl_down_sync(0xffffffffu, bi, off);
            combine(bd, bi, od, oi);
        }
        const int wid = tid >> 5;
        if ((tid & 31) == 0) { red.sd[wid] = bd; red.si[wid] = bi; }
        __syncthreads();

        const int par = t & 1;
        if (wid == 0) {
            // 16 warp partials; lanes 16-31 duplicate 0-15 (harmless for
            // max+lowest-index reduction).
            bd = red.sd[tid & 15];
            bi = red.si[tid & 15];
#pragma unroll
            for (int off = 8; off > 0; off >>= 1) {
                float od = __shfl_down_sync(0xffffffffu, bd, off);
                int   oi = __shfl_down_sync(0xffffffffu, bi, off);
                combine(bd, bi, od, oi);
            }
            if (tid == 0) {
                // Multicast this CTA's candidate into every rank's slot
                // (double-buffered by parity -> no WAR race across the single
                // cluster barrier below).
#pragma unroll
                for (int r = 0; r < CPB; r++) {
                    RedBuf* pr = cluster.map_shared_rank(&red, r);
                    pr->rd[par][rank] = bd;
                    pr->ri[par][rank] = bi;
                }
            }
        }
        cluster.sync();   // release/acquire: remote candidates now visible

        // Every thread deterministically reduces the 4 candidates locally.
        float wbd = red.rd[par][0];
        int   wbi = red.ri[par][0];
#pragma unroll
        for (int r = 1; r < CPB; r++) combine(wbd, wbi, red.rd[par][r], red.ri[par][r]);
        f = wbi;
    }
}

extern "C" void kernel_launch(void* const* d_in, const int* in_sizes, int n_in,
                              void* d_out, int out_size) {
    const float* coord = (const float*)d_in[0];
    const int*   finit = (const int*)d_in[1];   // int32: JAX x64-disabled downgrade
    float*       out   = (float*)d_out;  // [B*1024 idx | B*1024*3 coords], f32
    (void)in_sizes; (void)n_in; (void)out_size;

    cudaFuncSetAttribute(fps_kernel,
                         cudaFuncAttributeMaxDynamicSharedMemorySize, DYN_SMEM);

    const int n = BATCH * NPT;
    soa_transpose<<<(n + 255) / 256, 256>>>(coord, n);
    fps_kernel<<<BATCH * CPB, TH, DYN_SMEM>>>(finit, out);
}

// round 9
// speedup vs baseline: 1.2105x; 1.2105x over previous
#include <cuda_runtime.h>
#include <cooperative_groups.h>

namespace cg = cooperative_groups;

#define BATCH    32
#define NPT      100000
#define NSAMP    1024
#define CPB      4                   // CTAs (cluster size) per batch
#define CHUNK    (NPT / CPB)         // 25000 points per CTA
#define TH       512
#define SP       18944               // smem-resident points per CTA (= 37*512)
#define SPT      (SP / TH)           // 37
#define SR       (CHUNK - SP)        // 6056 points kept in registers
#define SRG      (SR / 4)            // 1514 float4 groups
#define T2       (SRG - 2 * TH)     // 490: threads owning a 3rd tail group
#define DYN_SMEM (SP * 3 * 4)        // 227328 bytes: float2 xy[SP] + float z[SP]

// SoA copies of the coordinates (scratch; __device__ globals are allowed).
__device__ float g_sx[BATCH * NPT];
__device__ float g_sy[BATCH * NPT];
__device__ float g_sz[BATCH * NPT];

__global__ void soa_transpose(const float* __restrict__ coord, int n) {
    int i = blockIdx.x * blockDim.x + threadIdx.x;
    if (i < n) {
        float x = coord[3 * i + 0];
        float y = coord[3 * i + 1];
        float z = coord[3 * i + 2];
        g_sx[i] = x;
        g_sy[i] = y;
        g_sz[i] = z;
    }
}

struct Cand {                // one CTA's argmax candidate, coords attached
    float d; int i;
    float x, y, z;
    int pad[3];              // 32B
};

struct RedBuf {
    Cand  c[2][CPB];         // double-buffered cluster candidate exchange
    float sd[16];            // per-warp partials
    int   si[16];
};

__device__ __forceinline__ void combine(float& bd, int& bi, float od, int oi) {
    // argmax with first-occurrence (lowest index) tie-break, matching jnp.argmax
    if (od > bd || (od == bd && oi < bi)) { bd = od; bi = oi; }
}

// XLA:GPU-matching distance: FMA-contracted, left-to-right 3-term reduce:
//   fma(dz, dz, fma(dy, dy, dx*dx))          -- DO NOT CHANGE (bit-exact match)
__device__ __forceinline__ float dist3(float px, float py, float pz,
                                       float cx, float cy, float cz) {
    float dx = __fsub_rn(px, cx);
    float dy = __fsub_rn(py, cy);
    float dz = __fsub_rn(pz, cz);
    return __fmaf_rn(dz, dz, __fmaf_rn(dy, dy, __fmul_rn(dx, dx)));
}

__global__ void __cluster_dims__(CPB, 1, 1) __launch_bounds__(TH, 1)
fps_kernel(const int* __restrict__ finit, float* __restrict__ out)
{
    extern __shared__ float smem[];
    __shared__ RedBuf red;

    cg::cluster_group cluster = cg::this_cluster();
    const int rank = (int)cluster.block_rank();
    const int b    = blockIdx.x / CPB;
    const int tid  = threadIdx.x;
    const int base = rank * CHUNK;

    const float* __restrict__ bx = g_sx + b * NPT;
    const float* __restrict__ by = g_sy + b * NPT;
    const float* __restrict__ bz = g_sz + b * NPT;

    float2* sxy = (float2*)smem;          // [SP] packed (x,y)
    float*  sz  = smem + 2 * SP;          // [SP]

    // Fill smem-resident slab once.
    for (int i = tid; i < SP; i += TH) {
        sxy[i] = make_float2(bx[base + i], by[base + i]);
        sz[i]  = bz[base + i];
    }
    __syncthreads();

    // Tail points: permanently register-resident (loaded once, float4 SoA).
    const float4* __restrict__ rx = (const float4*)(bx + base + SP);
    const float4* __restrict__ ry = (const float4*)(by + base + SP);
    const float4* __restrict__ rz = (const float4*)(bz + base + SP);

    float tx[12], ty[12], tz[12];
#pragma unroll
    for (int g = 0; g < 3; g++) {
        const int grp = g * TH + tid;
        if (g < 2 || tid < T2) {
            float4 x4 = rx[grp], y4 = ry[grp], z4 = rz[grp];
            tx[g*4+0]=x4.x; tx[g*4+1]=x4.y; tx[g*4+2]=x4.z; tx[g*4+3]=x4.w;
            ty[g*4+0]=y4.x; ty[g*4+1]=y4.y; ty[g*4+2]=y4.z; ty[g*4+3]=y4.w;
            tz[g*4+0]=z4.x; tz[g*4+1]=z4.y; tz[g*4+2]=z4.z; tz[g*4+3]=z4.w;
        } else {
#pragma unroll
            for (int j = 0; j < 4; j++) { tx[g*4+j]=0.f; ty[g*4+j]=0.f; tz[g*4+j]=0.f; }
        }
    }

    // Running min-distance arrays, register-resident.
    float dmin_s[SPT];
    float dmin_r[12];
#pragma unroll
    for (int k = 0; k < SPT; k++) dmin_s[k] = 1e10f;
#pragma unroll
    for (int k = 0; k < 12; k++)  dmin_r[k] = 1e10f;

    // Seeds are int32 (JAX x64-disabled downgrade of jnp.int64).
    int f = finit[b];
    float cx = bx[f], cy = by[f], cz = bz[f];   // uniform broadcast LDG, once

    // Record t=0 (the seed) up front.
    if (rank == 0 && tid == 32) {
        out[b * NSAMP + 0] = (float)f;
        float* so = out + BATCH * NSAMP + (b * NSAMP + 0) * 3;
        so[0] = cx; so[1] = cy; so[2] = cz;
    }

    for (int t = 0; t < NSAMP; t++) {
        float bd = -1.0f;    // distances are >= 0
        int   bk = 0;        // best k within smem slots (immediate-friendly)

        // SMEM-resident points: 2 LDS/pt. Indices ascend with k, so strict '>'
        // gives the lowest-index tie-break within a thread.
#pragma unroll
        for (int k = 0; k < SPT; k++) {
            const int p = k * TH + tid;
            float2 xy = sxy[p];
            float  dist = dist3(xy.x, xy.y, sz[p], cx, cy, cz);
            float  dm   = fminf(dmin_s[k], dist);
            dmin_s[k] = dm;
            bool  pr = dm > bd;
            bd = pr ? dm : bd;
            bk = pr ? k  : bk;
        }
        int bi = base + bk * TH + tid;

        // Register-resident tail (no loads). Tail indices > all smem indices,
        // ascending in slot, so strict '>' preserves first-occurrence ties.
#pragma unroll
        for (int g = 0; g < 3; g++) {
            if (g < 2 || tid < T2) {
                const int gi0 = base + SP + (g * TH + tid) * 4;
#pragma unroll
                for (int j = 0; j < 4; j++) {
                    const int s = g * 4 + j;
                    float dist = dist3(tx[s], ty[s], tz[s], cx, cy, cz);
                    float dm   = fminf(dmin_r[s], dist);
                    dmin_r[s] = dm;
                    if (dm > bd) { bd = dm; bi = gi0 + j; }
                }
            }
        }

        // Warp argmax (ties -> lowest index).
#pragma unroll
        for (int off = 16; off > 0; off >>= 1) {
            float od = __shfl_down_sync(0xffffffffu, bd, off);
            int   oi = __shfl_down_sync(0xffffffffu, bi, off);
            combine(bd, bi, od, oi);
        }
        const int wid = tid >> 5;
        if ((tid & 31) == 0) { red.sd[wid] = bd; red.si[wid] = bi; }
        __syncthreads();

        const int par = t & 1;
        if (wid == 0) {
            bd = red.sd[tid & 15];
            bi = red.si[tid & 15];
#pragma unroll
            for (int off = 8; off > 0; off >>= 1) {
                float od = __shfl_down_sync(0xffffffffu, bd, off);
                int   oi = __shfl_down_sync(0xffffffffu, bi, off);
                combine(bd, bi, od, oi);
            }
            if (tid == 0) {
                // Fetch candidate coords PRE-sync (smem if resident, else L2),
                // then multicast {d,i,x,y,z} into every rank's parity slot.
                float qx, qy, qz;
                const int loc = bi - base;
                if (loc < SP) {
                    float2 q = sxy[loc];
                    qx = q.x; qy = q.y; qz = sz[loc];
                } else {
                    qx = bx[bi]; qy = by[bi]; qz = bz[bi];
                }
#pragma unroll
                for (int r = 0; r < CPB; r++) {
                    RedBuf* pr = cluster.map_shared_rank(&red, r);
                    Cand* c = &pr->c[par][rank];
                    c->d = bd; c->i = bi;
                    c->x = qx; c->y = qy; c->z = qz;
                }
            }
        }
        cluster.sync();   // release/acquire: remote candidates now visible

        // Deterministic local reduce of the 4 candidates. Rank index ranges
        // are disjoint & ascending, so strict '>' keeps the lowest index.
        Cand w = red.c[par][0];
#pragma unroll
        for (int r = 1; r < CPB; r++) {
            const Cand& o = red.c[par][r];
            if (o.d > w.d) w = o;
        }
        f = w.i; cx = w.x; cy = w.y; cz = w.z;

        // Record t+1 using the broadcast winner (no global re-fetch).
        if (t < NSAMP - 1 && rank == 0 && tid == 32) {
            out[b * NSAMP + (t + 1)] = (float)f;
            float* so = out + BATCH * NSAMP + (b * NSAMP + (t + 1)) * 3;
            so[0] = cx; so[1] = cy; so[2] = cz;
        }
    }
}

extern "C" void kernel_launch(void* const* d_in, const int* in_sizes, int n_in,
                              void* d_out, int out_size) {
    const float* coord = (const float*)d_in[0];
    const int*   finit = (const int*)d_in[1];   // int32 (JAX x64 disabled)
    float*       out   = (float*)d_out;  // [B*1024 idx | B*1024*3 coords], f32
    (void)in_sizes; (void)n_in; (void)out_size;

    cudaFuncSetAttribute(fps_kernel,
                         cudaFuncAttributeMaxDynamicSharedMemorySize, DYN_SMEM);

    const int n = BATCH * NPT;
    soa_transpose<<<(n + 255) / 256, 256>>>(coord, n);
    fps_kernel<<<BATCH * CPB, TH, DYN_SMEM>>>(finit, out);
}

// round 10
// speedup vs baseline: 1.2757x; 1.0538x over previous
#include <cuda_runtime.h>
#include <cooperative_groups.h>
#include <cstdint>

namespace cg = cooperative_groups;

#define BATCH    32
#define NPT      100000
#define NSAMP    1024
#define CPB      4                    // CTAs (cluster size) per batch
#define CHUNK    (NPT / CPB)          // 25000 points per CTA
#define TH       512
#define KP       18                   // main smem pairs per thread
#define SPM      (KP * 2 * TH)        // 18432 main smem points
#define NEX      424                  // extra smem points (212 pairs, tid<212)
#define NEX2     (NEX / 2)            // 212
#define NSM      (SPM + NEX)          // 18856 smem points total
#define TAIL0    NSM                  // tail starts here; 25000-18856 = 6144
#define TPP      6                    // tail pairs per thread (12 points)
#define DYN_SMEM (NSM * 3 * 4)        // 226272 bytes SoA

// SoA copies of the coordinates (scratch; __device__ globals are allowed).
__device__ float g_sx[BATCH * NPT];
__device__ float g_sy[BATCH * NPT];
__device__ float g_sz[BATCH * NPT];

__global__ void soa_transpose(const float* __restrict__ coord, int n) {
    int i = blockIdx.x * blockDim.x + threadIdx.x;
    if (i < n) {
        float x = coord[3 * i + 0];
        float y = coord[3 * i + 1];
        float z = coord[3 * i + 2];
        g_sx[i] = x;
        g_sy[i] = y;
        g_sz[i] = z;
    }
}

struct Cand {                // one CTA's argmax candidate, coords attached
    float d; int i;
    float x, y, z;
    int pad[3];              // 32B
};

struct RedBuf {
    Cand  c[2][CPB];         // double-buffered cluster candidate exchange
    float sd[16];            // per-warp partials
    int   si[16];
};

// ---- packed f32x2 helpers (per-lane IEEE rn, bit-identical to scalar) ----
__device__ __forceinline__ uint64_t pack2(float a, float b) {
    uint64_t r; asm("mov.b64 %0, {%1,%2};" : "=l"(r) : "f"(a), "f"(b)); return r;
}
__device__ __forceinline__ void unpack2(uint64_t v, float& a, float& b) {
    asm("mov.b64 {%0,%1}, %2;" : "=f"(a), "=f"(b) : "l"(v));
}
__device__ __forceinline__ uint64_t addx2(uint64_t a, uint64_t b) {
    uint64_t r; asm("add.rn.f32x2 %0, %1, %2;" : "=l"(r) : "l"(a), "l"(b)); return r;
}
__device__ __forceinline__ uint64_t mulx2(uint64_t a, uint64_t b) {
    uint64_t r; asm("mul.rn.f32x2 %0, %1, %2;" : "=l"(r) : "l"(a), "l"(b)); return r;
}
__device__ __forceinline__ uint64_t fmax2(uint64_t a, uint64_t b, uint64_t c) {
    uint64_t r; asm("fma.rn.f32x2 %0, %1, %2, %3;" : "=l"(r) : "l"(a), "l"(b), "l"(c)); return r;
}

// XLA-matching distance for TWO points at once. Per lane:
//   dx = p + (-c)  (== p - c bitwise);  fma(dz,dz, fma(dy,dy, dx*dx))
// DO NOT change the rounding sequence (bit-exact trajectory match).
__device__ __forceinline__ void dist3x2(uint64_t xp, uint64_t yp, uint64_t zp,
                                        uint64_t ncx, uint64_t ncy, uint64_t ncz,
                                        float& d0, float& d1) {
    uint64_t dx = addx2(xp, ncx);
    uint64_t dy = addx2(yp, ncy);
    uint64_t dz = addx2(zp, ncz);
    uint64_t m  = mulx2(dx, dx);
    m = fmax2(dy, dy, m);
    m = fmax2(dz, dz, m);
    unpack2(m, d0, d1);
}

__global__ void __cluster_dims__(CPB, 1, 1) __launch_bounds__(TH, 1)
fps_kernel(const int* __restrict__ finit, float* __restrict__ out)
{
    extern __shared__ float smem[];
    __shared__ RedBuf red;

    cg::cluster_group cluster = cg::this_cluster();
    const int rank = (int)cluster.block_rank();
    const int b    = blockIdx.x / CPB;
    const int tid  = threadIdx.x;
    const int base = rank * CHUNK;

    const float* __restrict__ bx = g_sx + b * NPT;
    const float* __restrict__ by = g_sy + b * NPT;
    const float* __restrict__ bz = g_sz + b * NPT;

    float* sx = smem;
    float* sy = smem + NSM;
    float* sz = smem + 2 * NSM;

    // Fill smem-resident SoA slab once.
    for (int i = tid; i < NSM; i += TH) {
        sx[i] = bx[base + i];
        sy[i] = by[base + i];
        sz[i] = bz[base + i];
    }
    __syncthreads();

    const uint64_t* sx2 = (const uint64_t*)sx;   // pair views (8B aligned: NSM even)
    const uint64_t* sy2 = (const uint64_t*)sy;
    const uint64_t* sz2 = (const uint64_t*)sz;
    const uint64_t* ex2 = (const uint64_t*)(sx + SPM);
    const uint64_t* ey2 = (const uint64_t*)(sy + SPM);
    const uint64_t* ez2 = (const uint64_t*)(sz + SPM);

    // Tail points: permanently register-resident, pre-packed into f32x2 pairs.
    // (rank*25000 + 18856) divisible by 4 -> float4 aligned.
    const float4* __restrict__ rx = (const float4*)(bx + base + TAIL0);
    const float4* __restrict__ ry = (const float4*)(by + base + TAIL0);
    const float4* __restrict__ rz = (const float4*)(bz + base + TAIL0);

    uint64_t txp[TPP], typ[TPP], tzp[TPP];
#pragma unroll
    for (int g = 0; g < 3; g++) {
        const int grp = g * TH + tid;            // 6144/4 = 1536 = 3*TH exactly
        float4 x4 = rx[grp], y4 = ry[grp], z4 = rz[grp];
        txp[2*g] = pack2(x4.x, x4.y); txp[2*g+1] = pack2(x4.z, x4.w);
        typ[2*g] = pack2(y4.x, y4.y); typ[2*g+1] = pack2(y4.z, y4.w);
        tzp[2*g] = pack2(z4.x, z4.y); tzp[2*g+1] = pack2(z4.z, z4.w);
    }

    // Running min-distance arrays, register-resident.
    float dmin_s[2 * KP];
    float dmin_e[2];
    float dmin_r[2 * TPP];
#pragma unroll
    for (int k = 0; k < 2 * KP; k++)  dmin_s[k] = 1e10f;
    dmin_e[0] = 1e10f; dmin_e[1] = 1e10f;
#pragma unroll
    for (int k = 0; k < 2 * TPP; k++) dmin_r[k] = 1e10f;

    // Seeds are int32 (JAX x64-disabled downgrade of jnp.int64).
    int f = finit[b];
    float cx = bx[f], cy = by[f], cz = bz[f];   // uniform broadcast LDG, once

    // Record t=0 (the seed) up front.
    if (rank == 0 && tid == 32) {
        out[b * NSAMP + 0] = (float)f;
        float* so = out + BATCH * NSAMP + (b * NSAMP + 0) * 3;
        so[0] = cx; so[1] = cy; so[2] = cz;
    }

    for (int t = 0; t < NSAMP; t++) {
        // Negated centroid, broadcast-packed (negation is exact; add(p,-c) == sub(p,c)).
        const uint64_t ncx = pack2(-cx, -cx);
        const uint64_t ncy = pack2(-cy, -cy);
        const uint64_t ncz = pack2(-cz, -cz);

        float bd  = -1.0f;   // distances are >= 0
        int   bloc = 0;      // best local (chunk-relative) index

        // Main smem pairs. Per-thread local indices ascend across k and within
        // a pair (lo first), so strict '>' keeps the lowest index on ties.
#pragma unroll
        for (int k = 0; k < KP; k++) {
            const int q = k * TH + tid;
            float d0, d1;
            dist3x2(sx2[q], sy2[q], sz2[q], ncx, ncy, ncz, d0, d1);
            float dm0 = fminf(dmin_s[2*k],   d0); dmin_s[2*k]   = dm0;
            float dm1 = fminf(dmin_s[2*k+1], d1); dmin_s[2*k+1] = dm1;
            if (dm0 > bd) { bd = dm0; bloc = 2 * q; }
            if (dm1 > bd) { bd = dm1; bloc = 2 * q + 1; }
        }

        // Extra smem pairs (points SPM..SPM+423), threads 0..211 only.
        // Indices here are > all main indices and < tail indices: order OK.
        if (tid < NEX2) {
            float d0, d1;
            dist3x2(ex2[tid], ey2[tid], ez2[tid], ncx, ncy, ncz, d0, d1);
            float dm0 = fminf(dmin_e[0], d0); dmin_e[0] = dm0;
            float dm1 = fminf(dmin_e[1], d1); dmin_e[1] = dm1;
            const int p0 = SPM + 2 * tid;
            if (dm0 > bd) { bd = dm0; bloc = p0; }
            if (dm1 > bd) { bd = dm1; bloc = p0 + 1; }
        }

        // Register-resident tail pairs (no loads). Ascending local indices.
#pragma unroll
        for (int pp = 0; pp < TPP; pp++) {
            float d0, d1;
            dist3x2(txp[pp], typ[pp], tzp[pp], ncx, ncy, ncz, d0, d1);
            float dm0 = fminf(dmin_r[2*pp],   d0); dmin_r[2*pp]   = dm0;
            float dm1 = fminf(dmin_r[2*pp+1], d1); dmin_r[2*pp+1] = dm1;
            const int p0 = TAIL0 + ((pp >> 1) * TH + tid) * 4 + (pp & 1) * 2;
            if (dm0 > bd) { bd = dm0; bloc = p0; }
            if (dm1 > bd) { bd = dm1; bloc = p0 + 1; }
        }

        int bi = base + bloc;

        // Warp argmax via REDUX: distances >= 0, so f32 bits are monotone as
        // unsigned. Ties -> lowest index via reduce_min over tied lanes.
        unsigned u = __float_as_uint(bd);
        unsigned m = __reduce_max_sync(0xffffffffu, u);
        unsigned cnd = (u == m) ? (unsigned)bi : 0xffffffffu;
        unsigned wmin = __reduce_min_sync(0xffffffffu, cnd);
        const int wid = tid >> 5;
        if ((tid & 31) == 0) { red.sd[wid] = __uint_as_float(m); red.si[wid] = (int)wmin; }
        __syncthreads();

        const int par = t & 1;
        if (wid == 0) {
            unsigned u2 = __float_as_uint(red.sd[tid & 15]);  // lanes 16-31 dup: harmless
            int      i2 = red.si[tid & 15];
            unsigned m2 = __reduce_max_sync(0xffffffffu, u2);
            unsigned c2 = (u2 == m2) ? (unsigned)i2 : 0xffffffffu;
            unsigned w2 = __reduce_min_sync(0xffffffffu, c2);
            if (tid == 0) {
                const int gbi = (int)w2;
                const int loc = gbi - base;
                float qx, qy, qz;
                if (loc < NSM) { qx = sx[loc]; qy = sy[loc]; qz = sz[loc]; }
                else           { qx = bx[gbi]; qy = by[gbi]; qz = bz[gbi]; }
                float qd = __uint_as_float(m2);
#pragma unroll
                for (int r = 0; r < CPB; r++) {
                    RedBuf* pr = cluster.map_shared_rank(&red, r);
                    Cand* c = &pr->c[par][rank];
                    c->d = qd; c->i = gbi;
                    c->x = qx; c->y = qy; c->z = qz;
                }
            }
        }
        cluster.sync();   // release/acquire: remote candidates now visible

        // Deterministic local reduce of the 4 candidates. Rank index ranges
        // are disjoint & ascending, so strict '>' keeps the lowest index.
        Cand w = red.c[par][0];
#pragma unroll
        for (int r = 1; r < CPB; r++) {
            const Cand& o = red.c[par][r];
            if (o.d > w.d) w = o;
        }
        f = w.i; cx = w.x; cy = w.y; cz = w.z;

        // Record t+1 using the broadcast winner (no global re-fetch).
        if (t < NSAMP - 1 && rank == 0 && tid == 32) {
            out[b * NSAMP + (t + 1)] = (float)f;
            float* so = out + BATCH * NSAMP + (b * NSAMP + (t + 1)) * 3;
            so[0] = cx; so[1] = cy; so[2] = cz;
        }
    }
}

extern "C" void kernel_launch(void* const* d_in, const int* in_sizes, int n_in,
                              void* d_out, int out_size) {
    const float* coord = (const float*)d_in[0];
    const int*   finit = (const int*)d_in[1];   // int32 (JAX x64 disabled)
    float*       out   = (float*)d_out;  // [B*1024 idx | B*1024*3 coords], f32
    (void)in_sizes; (void)n_in; (void)out_size;

    cudaFuncSetAttribute(fps_kernel,
                         cudaFuncAttributeMaxDynamicSharedMemorySize, DYN_SMEM);

    const int n = BATCH * NPT;
    soa_transpose<<<(n + 255) / 256, 256>>>(coord, n);
    fps_kernel<<<BATCH * CPB, TH, DYN_SMEM>>>(finit, out);
}